// round 11
// baseline (speedup 1.0000x reference)
#include <cuda_runtime.h>

#define D     2048
#define SEQ   4096
#define BB    4
#define ROWS  16384      // BB*SEQ
#define RS    6          // ar_ssm rank
#define RF    21         // ffn rank
#define EPS   1e-6f

typedef unsigned long long ull;

// scratch (device globals — no allocations allowed)
__device__ float g_u [RS * ROWS];   // u transposed: [r][row]
__device__ float g_hs[RS * ROWS];   // scan states transposed: [r][row]
__device__ float g_g [ROWS * RF];   // gelu(t) per row

// -------- f32x2 helpers --------
__device__ __forceinline__ ull pk(float a, float b) {
    ull r; asm("mov.b64 %0,{%1,%2};" : "=l"(r) : "f"(a), "f"(b)); return r;
}
__device__ __forceinline__ ull pk1(float a) { return pk(a, a); }
__device__ __forceinline__ ull f2fma(ull a, ull b, ull c) {
    ull d; asm("fma.rn.f32x2 %0,%1,%2,%3;" : "=l"(d) : "l"(a), "l"(b), "l"(c));
    return d;
}
__device__ __forceinline__ void upk(ull v, float& a, float& b) {
    asm("mov.b64 {%0,%1},%2;" : "=f"(a), "=f"(b) : "l"(v));
}
__device__ __forceinline__ float wred(float v) {
#pragma unroll
    for (int off = 16; off > 0; off >>= 1)
        v += __shfl_xor_sync(0xffffffffu, v, off);
    return v;
}

// ============================================================================
// K1: per-row ssq(x) and u = rmsnorm(x,w1) @ U   (U*w1 folded into smem).
// 4 rows per warp; row pairs packed into f32x2 lanes.
// ============================================================================
__global__ void __launch_bounds__(256) k1_kernel(const float* __restrict__ x,
                                                 const float* __restrict__ w1,
                                                 const float* __restrict__ U) {
    extern __shared__ float Us[];                 // [RS][D]
    int tid = threadIdx.x;
    for (int d = tid; d < D; d += 256) {
        float w = w1[d];
#pragma unroll
        for (int r = 0; r < RS; r++) Us[r * D + d] = U[d * RS + r] * w;
    }
    __syncthreads();

    int lane = tid & 31;
    int gw = (blockIdx.x * 256 + tid) >> 5;
    int nw = (gridDim.x * 256) >> 5;

    for (int tile = gw; tile < ROWS / 4; tile += nw) {
        int row0 = tile * 4;
        const float* xp = x + (size_t)row0 * D;

        ull ss0 = 0ull, ss1 = 0ull;
        ull u20[RS], u21[RS];
#pragma unroll
        for (int r = 0; r < RS; r++) { u20[r] = 0ull; u21[r] = 0ull; }

#pragma unroll 1
        for (int it = 0; it < 16; it++) {
            int d0 = it * 128 + lane * 4;
            float xa[4], xb[4], xc[4], xd[4];
            *(float4*)xa = *(const float4*)(xp + d0);
            *(float4*)xb = *(const float4*)(xp + D + d0);
            *(float4*)xc = *(const float4*)(xp + 2 * D + d0);
            *(float4*)xd = *(const float4*)(xp + 3 * D + d0);
            float uw[RS][4];
#pragma unroll
            for (int r = 0; r < RS; r++)
                *(float4*)uw[r] = *(const float4*)(Us + r * D + d0);
#pragma unroll
            for (int d = 0; d < 4; d++) {
                ull p0 = pk(xa[d], xb[d]);
                ull p1 = pk(xc[d], xd[d]);
                ss0 = f2fma(p0, p0, ss0);
                ss1 = f2fma(p1, p1, ss1);
#pragma unroll
                for (int r = 0; r < RS; r++) {
                    ull w2 = pk1(uw[r][d]);
                    u20[r] = f2fma(p0, w2, u20[r]);
                    u21[r] = f2fma(p1, w2, u21[r]);
                }
            }
        }
        float ss[4], myu[4];
        { float a, b; upk(ss0, a, b); ss[0] = a; ss[1] = b;
                      upk(ss1, a, b); ss[2] = a; ss[3] = b; }
#pragma unroll
        for (int rr = 0; rr < 4; rr++) ss[rr] = wred(ss[rr]);
#pragma unroll
        for (int r = 0; r < RS; r++) {
            float a, b;
            upk(u20[r], a, b);
            a = wred(a); b = wred(b);
            if (lane == r) { myu[0] = a; myu[1] = b; }
            upk(u21[r], a, b);
            a = wred(a); b = wred(b);
            if (lane == r) { myu[2] = a; myu[3] = b; }
        }
#pragma unroll
        for (int rr = 0; rr < 4; rr++) {
            float inv = rsqrtf(ss[rr] * (1.0f / D) + EPS);
            if (lane < RS) g_u[lane * ROWS + row0 + rr] = inv * myu[rr];
        }
    }
}

// ============================================================================
// K2: linear recurrence h_s = a*h_{s-1} + u_s along S, per (b,r).
// 128 threads x 32 serial; Hillis-Steele over chunk carries with factor a^32.
// ============================================================================
__global__ void __launch_bounds__(128) k2_scan(const float* __restrict__ lam) {
    int b = blockIdx.x / RS, r = blockIdx.x % RS;
    float a = 1.0f / (1.0f + expf(-lam[r]));
    const float* up = g_u  + r * ROWS + b * SEQ;
    float*       hp = g_hs + r * ROWS + b * SEQ;
    int t = threadIdx.x;
    const int L = 32;

    float loc[L];
#pragma unroll
    for (int kk = 0; kk < L / 4; kk++)
        *(float4*)(loc + kk * 4) = *(const float4*)(up + t * L + kk * 4);

    float h = 0.0f;
#pragma unroll
    for (int k = 0; k < L; k++) { h = a * h + loc[k]; loc[k] = h; }

    float aL = a;
#pragma unroll
    for (int i = 0; i < 5; i++) aL = aL * aL;     // a^32

    __shared__ float sf[128];
    float T = h;
    sf[t] = T;
    __syncthreads();
    float m = aL;
    for (int off = 1; off < 128; off <<= 1) {
        float prev = (t >= off) ? sf[t - off] : 0.0f;
        __syncthreads();
        T += m * prev;
        sf[t] = T;
        m = m * m;
        __syncthreads();
    }
    float Hin = (t > 0) ? sf[t - 1] : 0.0f;
    float p = a;
#pragma unroll
    for (int k = 0; k < L; k++) { loc[k] = loc[k] + p * Hin; p *= a; }
#pragma unroll
    for (int kk = 0; kk < L / 4; kk++)
        *(float4*)(hp + t * L + kk * 4) = *(const float4*)(loc + kk * 4);
}

// ============================================================================
// K3a: x1 = x + h@V (recomputed, never stored); ssq(x1);
//      t = (norm2_w * x1 / rms) @ W1; store g = gelu(t) (21 floats/row).
// V (48KB) + W1^T*w2 (168KB) in smem; 1 CTA/SM persistent.
// ============================================================================
__global__ void __launch_bounds__(256) k3a_kernel(const float* __restrict__ x,
                                                  const float* __restrict__ V,
                                                  const float* __restrict__ w2,
                                                  const float* __restrict__ W1) {
    extern __shared__ float sm[];
    float* Vs  = sm;              // [RS][D]
    float* W1s = sm + RS * D;     // [RF][D] transposed, * norm2_w
    int tid = threadIdx.x;
    for (int i = tid; i < RS * D; i += 256) Vs[i] = V[i];
    for (int d = tid; d < D; d += 256) {
        float w = w2[d];
#pragma unroll
        for (int j = 0; j < RF; j++) W1s[j * D + d] = W1[d * RF + j] * w;
    }
    __syncthreads();

    int lane = tid & 31;
    int gw = (blockIdx.x * 256 + tid) >> 5;
    int nw = (gridDim.x * 256) >> 5;

    for (int tile = gw; tile < ROWS / 4; tile += nw) {
        int row0 = tile * 4;
        const float* xp = x + (size_t)row0 * D;

        ull h0[RS], h1[RS];
#pragma unroll
        for (int r = 0; r < RS; r++) {
            const float* hb = g_hs + r * ROWS + row0;
            h0[r] = pk(hb[0], hb[1]);
            h1[r] = pk(hb[2], hb[3]);
        }
        ull ss0 = 0ull, ss1 = 0ull;
        ull t0[RF], t1[RF];
#pragma unroll
        for (int j = 0; j < RF; j++) { t0[j] = 0ull; t1[j] = 0ull; }

#pragma unroll 1
        for (int it = 0; it < 16; it++) {
            int d0 = it * 128 + lane * 4;
            float xa[4], xb[4], xc[4], xd[4];
            *(float4*)xa = *(const float4*)(xp + d0);
            *(float4*)xb = *(const float4*)(xp + D + d0);
            *(float4*)xc = *(const float4*)(xp + 2 * D + d0);
            *(float4*)xd = *(const float4*)(xp + 3 * D + d0);
            float vv[RS][4];
#pragma unroll
            for (int r = 0; r < RS; r++)
                *(float4*)vv[r] = *(const float4*)(Vs + r * D + d0);

            ull x10[4], x11[4];
#pragma unroll
            for (int d = 0; d < 4; d++) {
                ull p0 = pk(xa[d], xb[d]);
                ull p1 = pk(xc[d], xd[d]);
#pragma unroll
                for (int r = 0; r < RS; r++) {
                    ull v2 = pk1(vv[r][d]);
                    p0 = f2fma(h0[r], v2, p0);
                    p1 = f2fma(h1[r], v2, p1);
                }
                x10[d] = p0; x11[d] = p1;
                ss0 = f2fma(p0, p0, ss0);
                ss1 = f2fma(p1, p1, ss1);
            }
#pragma unroll
            for (int j = 0; j < RF; j++) {
                float wv[4];
                *(float4*)wv = *(const float4*)(W1s + j * D + d0);
#pragma unroll
                for (int d = 0; d < 4; d++) {
                    ull w2p = pk1(wv[d]);
                    t0[j] = f2fma(x10[d], w2p, t0[j]);
                    t1[j] = f2fma(x11[d], w2p, t1[j]);
                }
            }
        }
        float ss[4], myt[4];
        { float a, b; upk(ss0, a, b); ss[0] = a; ss[1] = b;
                      upk(ss1, a, b); ss[2] = a; ss[3] = b; }
#pragma unroll
        for (int rr = 0; rr < 4; rr++) ss[rr] = wred(ss[rr]);
#pragma unroll
        for (int j = 0; j < RF; j++) {
            float a, b;
            upk(t0[j], a, b);
            a = wred(a); b = wred(b);
            if (lane == j) { myt[0] = a; myt[1] = b; }
            upk(t1[j], a, b);
            a = wred(a); b = wred(b);
            if (lane == j) { myt[2] = a; myt[3] = b; }
        }
#pragma unroll
        for (int rr = 0; rr < 4; rr++) {
            float inv = rsqrtf(ss[rr] * (1.0f / D) + EPS);
            if (lane < RF) {
                float tv = inv * myt[rr];
                float g = 0.5f * tv *
                    (1.0f + tanhf(0.7978845608028654f * (tv + 0.044715f * tv * tv * tv)));
                g_g[(size_t)(row0 + rr) * RF + lane] = g;
            }
        }
    }
}

// ============================================================================
// K3b: out = (x + h@V) + g @ W2.   V + W2 (216KB) in smem; 1 CTA/SM.
// ============================================================================
__global__ void __launch_bounds__(256) k3b_kernel(const float* __restrict__ x,
                                                  const float* __restrict__ V,
                                                  const float* __restrict__ W2,
                                                  float* __restrict__ out) {
    extern __shared__ float sm[];
    float* Vs  = sm;              // [RS][D]
    float* W2s = sm + RS * D;     // [RF][D]
    int tid = threadIdx.x;
    for (int i = tid; i < RS * D; i += 256) Vs[i] = V[i];
    for (int i = tid; i < RF * D; i += 256) W2s[i] = W2[i];
    __syncthreads();

    int lane = tid & 31;
    int gw = (blockIdx.x * 256 + tid) >> 5;
    int nw = (gridDim.x * 256) >> 5;

    for (int tile = gw; tile < ROWS / 4; tile += nw) {
        int row0 = tile * 4;
        const float* xp = x + (size_t)row0 * D;
        float*       op = out + (size_t)row0 * D;

        ull h0[RS], h1[RS];
#pragma unroll
        for (int r = 0; r < RS; r++) {
            const float* hb = g_hs + r * ROWS + row0;
            h0[r] = pk(hb[0], hb[1]);
            h1[r] = pk(hb[2], hb[3]);
        }
        ull gg0[RF], gg1[RF];
#pragma unroll
        for (int j = 0; j < RF; j++) {
            gg0[j] = pk(g_g[(size_t)(row0 + 0) * RF + j], g_g[(size_t)(row0 + 1) * RF + j]);
            gg1[j] = pk(g_g[(size_t)(row0 + 2) * RF + j], g_g[(size_t)(row0 + 3) * RF + j]);
        }

#pragma unroll 1
        for (int it = 0; it < 16; it++) {
            int d0 = it * 128 + lane * 4;
            float xa[4], xb[4], xc[4], xd[4];
            *(float4*)xa = *(const float4*)(xp + d0);
            *(float4*)xb = *(const float4*)(xp + D + d0);
            *(float4*)xc = *(const float4*)(xp + 2 * D + d0);
            *(float4*)xd = *(const float4*)(xp + 3 * D + d0);
            float vv[RS][4];
#pragma unroll
            for (int r = 0; r < RS; r++)
                *(float4*)vv[r] = *(const float4*)(Vs + r * D + d0);

            ull o0[4], o1[4];
#pragma unroll
            for (int d = 0; d < 4; d++) {
                ull p0 = pk(xa[d], xb[d]);
                ull p1 = pk(xc[d], xd[d]);
#pragma unroll
                for (int r = 0; r < RS; r++) {
                    ull v2 = pk1(vv[r][d]);
                    p0 = f2fma(h0[r], v2, p0);
                    p1 = f2fma(h1[r], v2, p1);
                }
                o0[d] = p0; o1[d] = p1;
            }
#pragma unroll
            for (int j = 0; j < RF; j++) {
                float wv[4];
                *(float4*)wv = *(const float4*)(W2s + j * D + d0);
#pragma unroll
                for (int d = 0; d < 4; d++) {
                    ull w2p = pk1(wv[d]);
                    o0[d] = f2fma(gg0[j], w2p, o0[d]);
                    o1[d] = f2fma(gg1[j], w2p, o1[d]);
                }
            }
            float oa[4], ob[4], oc[4], od[4];
#pragma unroll
            for (int d = 0; d < 4; d++) {
                upk(o0[d], oa[d], ob[d]);
                upk(o1[d], oc[d], od[d]);
            }
            *(float4*)(op + d0)         = *(float4*)oa;
            *(float4*)(op + D + d0)     = *(float4*)ob;
            *(float4*)(op + 2 * D + d0) = *(float4*)oc;
            *(float4*)(op + 3 * D + d0) = *(float4*)od;
        }
    }
}

// ============================================================================
extern "C" void kernel_launch(void* const* d_in, const int* in_sizes, int n_in,
                              void* d_out, int out_size) {
    const float* x   = (const float*)d_in[0];
    const float* n1w = (const float*)d_in[1];
    const float* U   = (const float*)d_in[2];
    const float* lam = (const float*)d_in[3];
    const float* V   = (const float*)d_in[4];
    const float* n2w = (const float*)d_in[5];
    const float* W1  = (const float*)d_in[6];
    const float* W2  = (const float*)d_in[7];
    float* out = (float*)d_out;

    const int smem1 = RS * D * (int)sizeof(float);          // 48 KB
    const int smem3 = (RS + RF) * D * (int)sizeof(float);   // 216 KB

    cudaFuncSetAttribute(k1_kernel,
                         cudaFuncAttributeMaxDynamicSharedMemorySize, smem1);
    cudaFuncSetAttribute(k3a_kernel,
                         cudaFuncAttributeMaxDynamicSharedMemorySize, smem3);
    cudaFuncSetAttribute(k3b_kernel,
                         cudaFuncAttributeMaxDynamicSharedMemorySize, smem3);

    k1_kernel<<<512, 256, smem1>>>(x, n1w, U);          // 4096 warp-tiles
    k2_scan<<<BB * RS, 128>>>(lam);                     // 24 blocks
    k3a_kernel<<<148, 256, smem3>>>(x, V, n2w, W1);     // persistent, 1 CTA/SM
    k3b_kernel<<<148, 256, smem3>>>(x, V, W2, out);
}

// round 12
// speedup vs baseline: 1.0202x; 1.0202x over previous
#include <cuda_runtime.h>

#define D     2048
#define SEQ   4096
#define BB    4
#define ROWS  16384      // BB*SEQ
#define RS    6          // ar_ssm rank
#define RF    21         // ffn rank
#define EPS   1e-6f

typedef unsigned long long ull;

// scratch (device globals — no allocations allowed)
__device__ float g_u [RS * ROWS];   // u transposed: [r][row]
__device__ float g_hs[RS * ROWS];   // scan states transposed: [r][row]
__device__ float g_g [ROWS * RF];   // gelu(t) per row

// -------- f32x2 helpers --------
__device__ __forceinline__ ull pk(float a, float b) {
    ull r; asm("mov.b64 %0,{%1,%2};" : "=l"(r) : "f"(a), "f"(b)); return r;
}
__device__ __forceinline__ ull pk1(float a) { return pk(a, a); }
__device__ __forceinline__ ull f2fma(ull a, ull b, ull c) {
    ull d; asm("fma.rn.f32x2 %0,%1,%2,%3;" : "=l"(d) : "l"(a), "l"(b), "l"(c));
    return d;
}
__device__ __forceinline__ void upk(ull v, float& a, float& b) {
    asm("mov.b64 {%0,%1},%2;" : "=f"(a), "=f"(b) : "l"(v));
}
__device__ __forceinline__ float wred(float v) {
#pragma unroll
    for (int off = 16; off > 0; off >>= 1)
        v += __shfl_xor_sync(0xffffffffu, v, off);
    return v;
}

// ============================================================================
// K1: per-row ssq(x) and u = rmsnorm(x,w1) @ U   (U*w1 folded into smem).
// 4 rows per warp; row pairs packed into f32x2; prefetched x loads.
// ============================================================================
__global__ void __launch_bounds__(256) k1_kernel(const float* __restrict__ x,
                                                 const float* __restrict__ w1,
                                                 const float* __restrict__ U) {
    extern __shared__ float Us[];                 // [RS][D]
    int tid = threadIdx.x;
    for (int d = tid; d < D; d += 256) {
        float w = w1[d];
#pragma unroll
        for (int r = 0; r < RS; r++) Us[r * D + d] = U[d * RS + r] * w;
    }
    __syncthreads();

    int lane = tid & 31;
    int gw = (blockIdx.x * 256 + tid) >> 5;
    int nw = (gridDim.x * 256) >> 5;

    for (int tile = gw; tile < ROWS / 4; tile += nw) {
        int row0 = tile * 4;
        const float* xp = x + (size_t)row0 * D;

        ull ss0 = 0ull, ss1 = 0ull;
        ull u20[RS], u21[RS];
#pragma unroll
        for (int r = 0; r < RS; r++) { u20[r] = 0ull; u21[r] = 0ull; }

        // prefetch it=0
        float4 xa = *(const float4*)(xp + lane * 4);
        float4 xb = *(const float4*)(xp + D + lane * 4);
        float4 xc = *(const float4*)(xp + 2 * D + lane * 4);
        float4 xd = *(const float4*)(xp + 3 * D + lane * 4);

#pragma unroll 1
        for (int it = 0; it < 16; it++) {
            int d0 = it * 128 + lane * 4;
            float4 na, nb, nc, nd;
            if (it != 15) {
                int dn = d0 + 128;
                na = *(const float4*)(xp + dn);
                nb = *(const float4*)(xp + D + dn);
                nc = *(const float4*)(xp + 2 * D + dn);
                nd = *(const float4*)(xp + 3 * D + dn);
            }
            float A[4], Bv[4], C[4], Dv[4];
            *(float4*)A = xa; *(float4*)Bv = xb; *(float4*)C = xc; *(float4*)Dv = xd;

            float uw[RS][4];
#pragma unroll
            for (int r = 0; r < RS; r++)
                *(float4*)uw[r] = *(const float4*)(Us + r * D + d0);
#pragma unroll
            for (int d = 0; d < 4; d++) {
                ull p0 = pk(A[d], Bv[d]);
                ull p1 = pk(C[d], Dv[d]);
                ss0 = f2fma(p0, p0, ss0);
                ss1 = f2fma(p1, p1, ss1);
#pragma unroll
                for (int r = 0; r < RS; r++) {
                    ull w2 = pk1(uw[r][d]);
                    u20[r] = f2fma(p0, w2, u20[r]);
                    u21[r] = f2fma(p1, w2, u21[r]);
                }
            }
            xa = na; xb = nb; xc = nc; xd = nd;
        }
        float ss[4], myu[4];
        { float a, b; upk(ss0, a, b); ss[0] = a; ss[1] = b;
                      upk(ss1, a, b); ss[2] = a; ss[3] = b; }
#pragma unroll
        for (int rr = 0; rr < 4; rr++) ss[rr] = wred(ss[rr]);
#pragma unroll
        for (int r = 0; r < RS; r++) {
            float a, b;
            upk(u20[r], a, b);
            a = wred(a); b = wred(b);
            if (lane == r) { myu[0] = a; myu[1] = b; }
            upk(u21[r], a, b);
            a = wred(a); b = wred(b);
            if (lane == r) { myu[2] = a; myu[3] = b; }
        }
#pragma unroll
        for (int rr = 0; rr < 4; rr++) {
            float inv = rsqrtf(ss[rr] * (1.0f / D) + EPS);
            if (lane < RS) g_u[lane * ROWS + row0 + rr] = inv * myu[rr];
        }
    }
}

// ============================================================================
// K2: linear recurrence h_s = a*h_{s-1} + u_s along S, per (b,r).
// ============================================================================
__global__ void __launch_bounds__(128) k2_scan(const float* __restrict__ lam) {
    int b = blockIdx.x / RS, r = blockIdx.x % RS;
    float a = 1.0f / (1.0f + expf(-lam[r]));
    const float* up = g_u  + r * ROWS + b * SEQ;
    float*       hp = g_hs + r * ROWS + b * SEQ;
    int t = threadIdx.x;
    const int L = 32;

    float loc[L];
#pragma unroll
    for (int kk = 0; kk < L / 4; kk++)
        *(float4*)(loc + kk * 4) = *(const float4*)(up + t * L + kk * 4);

    float h = 0.0f;
#pragma unroll
    for (int k = 0; k < L; k++) { h = a * h + loc[k]; loc[k] = h; }

    float aL = a;
#pragma unroll
    for (int i = 0; i < 5; i++) aL = aL * aL;     // a^32

    __shared__ float sf[128];
    float T = h;
    sf[t] = T;
    __syncthreads();
    float m = aL;
    for (int off = 1; off < 128; off <<= 1) {
        float prev = (t >= off) ? sf[t - off] : 0.0f;
        __syncthreads();
        T += m * prev;
        sf[t] = T;
        m = m * m;
        __syncthreads();
    }
    float Hin = (t > 0) ? sf[t - 1] : 0.0f;
    float p = a;
#pragma unroll
    for (int k = 0; k < L; k++) { loc[k] = loc[k] + p * Hin; p *= a; }
#pragma unroll
    for (int kk = 0; kk < L / 4; kk++)
        *(float4*)(hp + t * L + kk * 4) = *(const float4*)(loc + kk * 4);
}

// ============================================================================
// K3a: x1 = x + h@V (recomputed); ssq(x1); t = (w2*x1/rms)@W1; g = gelu(t).
// V + W1^T*w2 in smem (216KB). 384 threads (12 warps/SM), prefetched x.
// ============================================================================
#define T3A 384
__global__ void __launch_bounds__(T3A) k3a_kernel(const float* __restrict__ x,
                                                  const float* __restrict__ V,
                                                  const float* __restrict__ w2,
                                                  const float* __restrict__ W1) {
    extern __shared__ float sm[];
    float* Vs  = sm;              // [RS][D]
    float* W1s = sm + RS * D;     // [RF][D] transposed, * norm2_w
    int tid = threadIdx.x;
    for (int i = tid; i < RS * D; i += T3A) Vs[i] = V[i];
    for (int d = tid; d < D; d += T3A) {
        float w = w2[d];
#pragma unroll
        for (int j = 0; j < RF; j++) W1s[j * D + d] = W1[d * RF + j] * w;
    }
    __syncthreads();

    int lane = tid & 31;
    int gw = (blockIdx.x * T3A + tid) >> 5;
    int nw = (gridDim.x * T3A) >> 5;

    for (int tile = gw; tile < ROWS / 4; tile += nw) {
        int row0 = tile * 4;
        const float* xp = x + (size_t)row0 * D;

        ull h0[RS], h1[RS];
#pragma unroll
        for (int r = 0; r < RS; r++) {
            const float* hb = g_hs + r * ROWS + row0;
            h0[r] = pk(hb[0], hb[1]);
            h1[r] = pk(hb[2], hb[3]);
        }
        ull ss0 = 0ull, ss1 = 0ull;
        ull t0[RF], t1[RF];
#pragma unroll
        for (int j = 0; j < RF; j++) { t0[j] = 0ull; t1[j] = 0ull; }

        float4 xa = *(const float4*)(xp + lane * 4);
        float4 xb = *(const float4*)(xp + D + lane * 4);
        float4 xc = *(const float4*)(xp + 2 * D + lane * 4);
        float4 xd = *(const float4*)(xp + 3 * D + lane * 4);

#pragma unroll 1
        for (int it = 0; it < 16; it++) {
            int d0 = it * 128 + lane * 4;
            float4 na, nb, nc, nd;
            if (it != 15) {
                int dn = d0 + 128;
                na = *(const float4*)(xp + dn);
                nb = *(const float4*)(xp + D + dn);
                nc = *(const float4*)(xp + 2 * D + dn);
                nd = *(const float4*)(xp + 3 * D + dn);
            }
            float A[4], Bv[4], C[4], Dv[4];
            *(float4*)A = xa; *(float4*)Bv = xb; *(float4*)C = xc; *(float4*)Dv = xd;

            float vv[RS][4];
#pragma unroll
            for (int r = 0; r < RS; r++)
                *(float4*)vv[r] = *(const float4*)(Vs + r * D + d0);

            ull x10[4], x11[4];
#pragma unroll
            for (int d = 0; d < 4; d++) {
                ull p0 = pk(A[d], Bv[d]);
                ull p1 = pk(C[d], Dv[d]);
#pragma unroll
                for (int r = 0; r < RS; r++) {
                    ull v2 = pk1(vv[r][d]);
                    p0 = f2fma(h0[r], v2, p0);
                    p1 = f2fma(h1[r], v2, p1);
                }
                x10[d] = p0; x11[d] = p1;
                ss0 = f2fma(p0, p0, ss0);
                ss1 = f2fma(p1, p1, ss1);
            }
#pragma unroll
            for (int j = 0; j < RF; j++) {
                float wv[4];
                *(float4*)wv = *(const float4*)(W1s + j * D + d0);
#pragma unroll
                for (int d = 0; d < 4; d++) {
                    ull w2p = pk1(wv[d]);
                    t0[j] = f2fma(x10[d], w2p, t0[j]);
                    t1[j] = f2fma(x11[d], w2p, t1[j]);
                }
            }
            xa = na; xb = nb; xc = nc; xd = nd;
        }
        float ss[4], myt[4];
        { float a, b; upk(ss0, a, b); ss[0] = a; ss[1] = b;
                      upk(ss1, a, b); ss[2] = a; ss[3] = b; }
#pragma unroll
        for (int rr = 0; rr < 4; rr++) ss[rr] = wred(ss[rr]);
#pragma unroll
        for (int j = 0; j < RF; j++) {
            float a, b;
            upk(t0[j], a, b);
            a = wred(a); b = wred(b);
            if (lane == j) { myt[0] = a; myt[1] = b; }
            upk(t1[j], a, b);
            a = wred(a); b = wred(b);
            if (lane == j) { myt[2] = a; myt[3] = b; }
        }
#pragma unroll
        for (int rr = 0; rr < 4; rr++) {
            float inv = rsqrtf(ss[rr] * (1.0f / D) + EPS);
            if (lane < RF) {
                float tv = inv * myt[rr];
                float g = 0.5f * tv *
                    (1.0f + tanhf(0.7978845608028654f * (tv + 0.044715f * tv * tv * tv)));
                g_g[(size_t)(row0 + rr) * RF + lane] = g;
            }
        }
    }
}

// ============================================================================
// K3b: out = (x + h@V) + g @ W2.
// 512 threads (16 warps/SM); gg staged in per-warp smem (saves 84 regs);
// prefetched x loads. smem: V(48K)+W2(168K)+gg stage(5.25K) = 221.3KB.
// ============================================================================
#define T3B 512
__global__ void __launch_bounds__(T3B) k3b_kernel(const float* __restrict__ x,
                                                  const float* __restrict__ V,
                                                  const float* __restrict__ W2,
                                                  float* __restrict__ out) {
    extern __shared__ float sm[];
    float* Vs  = sm;              // [RS][D]
    float* W2s = sm + RS * D;     // [RF][D]
    ull*   gW  = (ull*)(sm + (RS + RF) * D);   // [nwarps][RF][2]
    int tid = threadIdx.x;
    for (int i = tid; i < RS * D; i += T3B) Vs[i] = V[i];
    for (int i = tid; i < RF * D; i += T3B) W2s[i] = W2[i];
    __syncthreads();

    int lane = tid & 31;
    int wid = tid >> 5;
    ull* gw = gW + wid * (RF * 2);

    int gwid = (blockIdx.x * T3B + tid) >> 5;
    int nw = (gridDim.x * T3B) >> 5;

    for (int tile = gwid; tile < ROWS / 4; tile += nw) {
        int row0 = tile * 4;
        const float* xp = x + (size_t)row0 * D;
        float*       op = out + (size_t)row0 * D;

        ull h0[RS], h1[RS];
#pragma unroll
        for (int r = 0; r < RS; r++) {
            const float* hb = g_hs + r * ROWS + row0;
            h0[r] = pk(hb[0], hb[1]);
            h1[r] = pk(hb[2], hb[3]);
        }
        // stage gg for this tile in per-warp smem
        __syncwarp();
        if (lane < RF) {
            const float* gp = g_g + (size_t)row0 * RF + lane;
            gw[lane * 2]     = pk(gp[0],      gp[RF]);
            gw[lane * 2 + 1] = pk(gp[2 * RF], gp[3 * RF]);
        }
        __syncwarp();

        float4 xa = *(const float4*)(xp + lane * 4);
        float4 xb = *(const float4*)(xp + D + lane * 4);
        float4 xc = *(const float4*)(xp + 2 * D + lane * 4);
        float4 xd = *(const float4*)(xp + 3 * D + lane * 4);

#pragma unroll 1
        for (int it = 0; it < 16; it++) {
            int d0 = it * 128 + lane * 4;
            float4 na, nb, nc, nd;
            if (it != 15) {
                int dn = d0 + 128;
                na = *(const float4*)(xp + dn);
                nb = *(const float4*)(xp + D + dn);
                nc = *(const float4*)(xp + 2 * D + dn);
                nd = *(const float4*)(xp + 3 * D + dn);
            }
            float A[4], Bv[4], C[4], Dv[4];
            *(float4*)A = xa; *(float4*)Bv = xb; *(float4*)C = xc; *(float4*)Dv = xd;

            float vv[RS][4];
#pragma unroll
            for (int r = 0; r < RS; r++)
                *(float4*)vv[r] = *(const float4*)(Vs + r * D + d0);

            ull o0[4], o1[4];
#pragma unroll
            for (int d = 0; d < 4; d++) {
                ull p0 = pk(A[d], Bv[d]);
                ull p1 = pk(C[d], Dv[d]);
#pragma unroll
                for (int r = 0; r < RS; r++) {
                    ull v2 = pk1(vv[r][d]);
                    p0 = f2fma(h0[r], v2, p0);
                    p1 = f2fma(h1[r], v2, p1);
                }
                o0[d] = p0; o1[d] = p1;
            }
#pragma unroll
            for (int j = 0; j < RF; j++) {
                ulonglong2 gj = *(const ulonglong2*)(gw + j * 2);  // broadcast LDS.128
                float wv[4];
                *(float4*)wv = *(const float4*)(W2s + j * D + d0);
#pragma unroll
                for (int d = 0; d < 4; d++) {
                    ull w2p = pk1(wv[d]);
                    o0[d] = f2fma(gj.x, w2p, o0[d]);
                    o1[d] = f2fma(gj.y, w2p, o1[d]);
                }
            }
            float oa[4], ob[4], oc[4], od[4];
#pragma unroll
            for (int d = 0; d < 4; d++) {
                upk(o0[d], oa[d], ob[d]);
                upk(o1[d], oc[d], od[d]);
            }
            *(float4*)(op + d0)         = *(float4*)oa;
            *(float4*)(op + D + d0)     = *(float4*)ob;
            *(float4*)(op + 2 * D + d0) = *(float4*)oc;
            *(float4*)(op + 3 * D + d0) = *(float4*)od;

            xa = na; xb = nb; xc = nc; xd = nd;
        }
    }
}

// ============================================================================
extern "C" void kernel_launch(void* const* d_in, const int* in_sizes, int n_in,
                              void* d_out, int out_size) {
    const float* x   = (const float*)d_in[0];
    const float* n1w = (const float*)d_in[1];
    const float* U   = (const float*)d_in[2];
    const float* lam = (const float*)d_in[3];
    const float* V   = (const float*)d_in[4];
    const float* n2w = (const float*)d_in[5];
    const float* W1  = (const float*)d_in[6];
    const float* W2  = (const float*)d_in[7];
    float* out = (float*)d_out;

    const int smem1  = RS * D * (int)sizeof(float);            // 48 KB
    const int smem3a = (RS + RF) * D * (int)sizeof(float);     // 216 KB
    const int smem3b = smem3a + (T3B / 32) * RF * 2 * (int)sizeof(ull); // +5.25 KB

    cudaFuncSetAttribute(k1_kernel,
                         cudaFuncAttributeMaxDynamicSharedMemorySize, smem1);
    cudaFuncSetAttribute(k3a_kernel,
                         cudaFuncAttributeMaxDynamicSharedMemorySize, smem3a);
    cudaFuncSetAttribute(k3b_kernel,
                         cudaFuncAttributeMaxDynamicSharedMemorySize, smem3b);

    k1_kernel<<<512, 256, smem1>>>(x, n1w, U);
    k2_scan<<<BB * RS, 128>>>(lam);
    k3a_kernel<<<148, T3A, smem3a>>>(x, V, n2w, W1);
    k3b_kernel<<<148, T3B, smem3b>>>(x, V, W2, out);
}

// round 13
// speedup vs baseline: 1.0333x; 1.0128x over previous
#include <cuda_runtime.h>

#define D     2048
#define SEQ   4096
#define BB    4
#define ROWS  16384      // BB*SEQ
#define RS    6          // ar_ssm rank
#define RF    21         // ffn rank
#define EPS   1e-6f

typedef unsigned long long ull;

// scratch (device globals — no allocations allowed)
__device__ float g_u [RS * ROWS];   // u transposed: [r][row]
__device__ float g_hs[RS * ROWS];   // scan states transposed: [r][row]
__device__ float g_g [ROWS * RF];   // gelu(t) per row

// -------- f32x2 helpers --------
__device__ __forceinline__ ull pk(float a, float b) {
    ull r; asm("mov.b64 %0,{%1,%2};" : "=l"(r) : "f"(a), "f"(b)); return r;
}
__device__ __forceinline__ ull pk1(float a) { return pk(a, a); }
__device__ __forceinline__ ull f2fma(ull a, ull b, ull c) {
    ull d; asm("fma.rn.f32x2 %0,%1,%2,%3;" : "=l"(d) : "l"(a), "l"(b), "l"(c));
    return d;
}
__device__ __forceinline__ void upk(ull v, float& a, float& b) {
    asm("mov.b64 {%0,%1},%2;" : "=f"(a), "=f"(b) : "l"(v));
}
__device__ __forceinline__ float wred(float v) {
#pragma unroll
    for (int off = 16; off > 0; off >>= 1)
        v += __shfl_xor_sync(0xffffffffu, v, off);
    return v;
}

// ============================================================================
// K1: per-row ssq(x) and u = rmsnorm(x,w1) @ U   (U*w1 folded into smem).
// 4 rows per warp; row pairs packed into f32x2; prefetched x loads.
// ============================================================================
__global__ void __launch_bounds__(256) k1_kernel(const float* __restrict__ x,
                                                 const float* __restrict__ w1,
                                                 const float* __restrict__ U) {
    extern __shared__ float Us[];                 // [RS][D]
    int tid = threadIdx.x;
    for (int d = tid; d < D; d += 256) {
        float w = w1[d];
#pragma unroll
        for (int r = 0; r < RS; r++) Us[r * D + d] = U[d * RS + r] * w;
    }
    __syncthreads();

    int lane = tid & 31;
    int gw = (blockIdx.x * 256 + tid) >> 5;
    int nw = (gridDim.x * 256) >> 5;

    for (int tile = gw; tile < ROWS / 4; tile += nw) {
        int row0 = tile * 4;
        const float* xp = x + (size_t)row0 * D;

        ull ss0 = 0ull, ss1 = 0ull;
        ull u20[RS], u21[RS];
#pragma unroll
        for (int r = 0; r < RS; r++) { u20[r] = 0ull; u21[r] = 0ull; }

        // prefetch it=0
        float4 xa = *(const float4*)(xp + lane * 4);
        float4 xb = *(const float4*)(xp + D + lane * 4);
        float4 xc = *(const float4*)(xp + 2 * D + lane * 4);
        float4 xd = *(const float4*)(xp + 3 * D + lane * 4);

#pragma unroll 1
        for (int it = 0; it < 16; it++) {
            int d0 = it * 128 + lane * 4;
            float4 na, nb, nc, nd;
            if (it != 15) {
                int dn = d0 + 128;
                na = *(const float4*)(xp + dn);
                nb = *(const float4*)(xp + D + dn);
                nc = *(const float4*)(xp + 2 * D + dn);
                nd = *(const float4*)(xp + 3 * D + dn);
            }
            float A[4], Bv[4], C[4], Dv[4];
            *(float4*)A = xa; *(float4*)Bv = xb; *(float4*)C = xc; *(float4*)Dv = xd;

            float uw[RS][4];
#pragma unroll
            for (int r = 0; r < RS; r++)
                *(float4*)uw[r] = *(const float4*)(Us + r * D + d0);
#pragma unroll
            for (int d = 0; d < 4; d++) {
                ull p0 = pk(A[d], Bv[d]);
                ull p1 = pk(C[d], Dv[d]);
                ss0 = f2fma(p0, p0, ss0);
                ss1 = f2fma(p1, p1, ss1);
#pragma unroll
                for (int r = 0; r < RS; r++) {
                    ull w2 = pk1(uw[r][d]);
                    u20[r] = f2fma(p0, w2, u20[r]);
                    u21[r] = f2fma(p1, w2, u21[r]);
                }
            }
            xa = na; xb = nb; xc = nc; xd = nd;
        }
        float ss[4], myu[4];
        { float a, b; upk(ss0, a, b); ss[0] = a; ss[1] = b;
                      upk(ss1, a, b); ss[2] = a; ss[3] = b; }
#pragma unroll
        for (int rr = 0; rr < 4; rr++) ss[rr] = wred(ss[rr]);
#pragma unroll
        for (int r = 0; r < RS; r++) {
            float a, b;
            upk(u20[r], a, b);
            a = wred(a); b = wred(b);
            if (lane == r) { myu[0] = a; myu[1] = b; }
            upk(u21[r], a, b);
            a = wred(a); b = wred(b);
            if (lane == r) { myu[2] = a; myu[3] = b; }
        }
#pragma unroll
        for (int rr = 0; rr < 4; rr++) {
            float inv = rsqrtf(ss[rr] * (1.0f / D) + EPS);
            if (lane < RS) g_u[lane * ROWS + row0 + rr] = inv * myu[rr];
        }
    }
}

// ============================================================================
// K2: linear recurrence h_s = a*h_{s-1} + u_s along S, per (b,r).
// ============================================================================
__global__ void __launch_bounds__(128) k2_scan(const float* __restrict__ lam) {
    int b = blockIdx.x / RS, r = blockIdx.x % RS;
    float a = 1.0f / (1.0f + expf(-lam[r]));
    const float* up = g_u  + r * ROWS + b * SEQ;
    float*       hp = g_hs + r * ROWS + b * SEQ;
    int t = threadIdx.x;
    const int L = 32;

    float loc[L];
#pragma unroll
    for (int kk = 0; kk < L / 4; kk++)
        *(float4*)(loc + kk * 4) = *(const float4*)(up + t * L + kk * 4);

    float h = 0.0f;
#pragma unroll
    for (int k = 0; k < L; k++) { h = a * h + loc[k]; loc[k] = h; }

    float aL = a;
#pragma unroll
    for (int i = 0; i < 5; i++) aL = aL * aL;     // a^32

    __shared__ float sf[128];
    float T = h;
    sf[t] = T;
    __syncthreads();
    float m = aL;
    for (int off = 1; off < 128; off <<= 1) {
        float prev = (t >= off) ? sf[t - off] : 0.0f;
        __syncthreads();
        T += m * prev;
        sf[t] = T;
        m = m * m;
        __syncthreads();
    }
    float Hin = (t > 0) ? sf[t - 1] : 0.0f;
    float p = a;
#pragma unroll
    for (int k = 0; k < L; k++) { loc[k] = loc[k] + p * Hin; p *= a; }
#pragma unroll
    for (int kk = 0; kk < L / 4; kk++)
        *(float4*)(hp + t * L + kk * 4) = *(const float4*)(loc + kk * 4);
}

// ============================================================================
// K3a: x1 = x + h@V (recomputed); ssq(x1); t = (w2*x1/rms)@W1; g = gelu(t).
// V + W1^T*w2 in smem (216KB). 384 threads (12 warps/SM), prefetched x.
// ============================================================================
#define T3A 384
__global__ void __launch_bounds__(T3A) k3a_kernel(const float* __restrict__ x,
                                                  const float* __restrict__ V,
                                                  const float* __restrict__ w2,
                                                  const float* __restrict__ W1) {
    extern __shared__ float sm[];
    float* Vs  = sm;              // [RS][D]
    float* W1s = sm + RS * D;     // [RF][D] transposed, * norm2_w
    int tid = threadIdx.x;
    for (int i = tid; i < RS * D; i += T3A) Vs[i] = V[i];
    for (int d = tid; d < D; d += T3A) {
        float w = w2[d];
#pragma unroll
        for (int j = 0; j < RF; j++) W1s[j * D + d] = W1[d * RF + j] * w;
    }
    __syncthreads();

    int lane = tid & 31;
    int gw = (blockIdx.x * T3A + tid) >> 5;
    int nw = (gridDim.x * T3A) >> 5;

    for (int tile = gw; tile < ROWS / 4; tile += nw) {
        int row0 = tile * 4;
        const float* xp = x + (size_t)row0 * D;

        ull h0[RS], h1[RS];
#pragma unroll
        for (int r = 0; r < RS; r++) {
            const float* hb = g_hs + r * ROWS + row0;
            h0[r] = pk(hb[0], hb[1]);
            h1[r] = pk(hb[2], hb[3]);
        }
        ull ss0 = 0ull, ss1 = 0ull;
        ull t0[RF], t1[RF];
#pragma unroll
        for (int j = 0; j < RF; j++) { t0[j] = 0ull; t1[j] = 0ull; }

        float4 xa = *(const float4*)(xp + lane * 4);
        float4 xb = *(const float4*)(xp + D + lane * 4);
        float4 xc = *(const float4*)(xp + 2 * D + lane * 4);
        float4 xd = *(const float4*)(xp + 3 * D + lane * 4);

#pragma unroll 1
        for (int it = 0; it < 16; it++) {
            int d0 = it * 128 + lane * 4;
            float4 na, nb, nc, nd;
            if (it != 15) {
                int dn = d0 + 128;
                na = *(const float4*)(xp + dn);
                nb = *(const float4*)(xp + D + dn);
                nc = *(const float4*)(xp + 2 * D + dn);
                nd = *(const float4*)(xp + 3 * D + dn);
            }
            float A[4], Bv[4], C[4], Dv[4];
            *(float4*)A = xa; *(float4*)Bv = xb; *(float4*)C = xc; *(float4*)Dv = xd;

            float vv[RS][4];
#pragma unroll
            for (int r = 0; r < RS; r++)
                *(float4*)vv[r] = *(const float4*)(Vs + r * D + d0);

            ull x10[4], x11[4];
#pragma unroll
            for (int d = 0; d < 4; d++) {
                ull p0 = pk(A[d], Bv[d]);
                ull p1 = pk(C[d], Dv[d]);
#pragma unroll
                for (int r = 0; r < RS; r++) {
                    ull v2 = pk1(vv[r][d]);
                    p0 = f2fma(h0[r], v2, p0);
                    p1 = f2fma(h1[r], v2, p1);
                }
                x10[d] = p0; x11[d] = p1;
                ss0 = f2fma(p0, p0, ss0);
                ss1 = f2fma(p1, p1, ss1);
            }
#pragma unroll
            for (int j = 0; j < RF; j++) {
                float wv[4];
                *(float4*)wv = *(const float4*)(W1s + j * D + d0);
#pragma unroll
                for (int d = 0; d < 4; d++) {
                    ull w2p = pk1(wv[d]);
                    t0[j] = f2fma(x10[d], w2p, t0[j]);
                    t1[j] = f2fma(x11[d], w2p, t1[j]);
                }
            }
            xa = na; xb = nb; xc = nc; xd = nd;
        }
        float ss[4], myt[4];
        { float a, b; upk(ss0, a, b); ss[0] = a; ss[1] = b;
                      upk(ss1, a, b); ss[2] = a; ss[3] = b; }
#pragma unroll
        for (int rr = 0; rr < 4; rr++) ss[rr] = wred(ss[rr]);
#pragma unroll
        for (int j = 0; j < RF; j++) {
            float a, b;
            upk(t0[j], a, b);
            a = wred(a); b = wred(b);
            if (lane == j) { myt[0] = a; myt[1] = b; }
            upk(t1[j], a, b);
            a = wred(a); b = wred(b);
            if (lane == j) { myt[2] = a; myt[3] = b; }
        }
#pragma unroll
        for (int rr = 0; rr < 4; rr++) {
            float inv = rsqrtf(ss[rr] * (1.0f / D) + EPS);
            if (lane < RF) {
                float tv = inv * myt[rr];
                float g = 0.5f * tv *
                    (1.0f + tanhf(0.7978845608028654f * (tv + 0.044715f * tv * tv * tv)));
                g_g[(size_t)(row0 + rr) * RF + lane] = g;
            }
        }
    }
}

// ============================================================================
// K3b: out = (x + h@V) + g @ W2.
// 512 threads (16 warps/SM); gg staged in per-warp smem (saves 84 regs);
// prefetched x loads. smem: V(48K)+W2(168K)+gg stage(5.25K) = 221.3KB.
// ============================================================================
#define T3B 512
__global__ void __launch_bounds__(T3B) k3b_kernel(const float* __restrict__ x,
                                                  const float* __restrict__ V,
                                                  const float* __restrict__ W2,
                                                  float* __restrict__ out) {
    extern __shared__ float sm[];
    float* Vs  = sm;              // [RS][D]
    float* W2s = sm + RS * D;     // [RF][D]
    ull*   gW  = (ull*)(sm + (RS + RF) * D);   // [nwarps][RF][2]
    int tid = threadIdx.x;
    for (int i = tid; i < RS * D; i += T3B) Vs[i] = V[i];
    for (int i = tid; i < RF * D; i += T3B) W2s[i] = W2[i];
    __syncthreads();

    int lane = tid & 31;
    int wid = tid >> 5;
    ull* gw = gW + wid * (RF * 2);

    int gwid = (blockIdx.x * T3B + tid) >> 5;
    int nw = (gridDim.x * T3B) >> 5;

    for (int tile = gwid; tile < ROWS / 4; tile += nw) {
        int row0 = tile * 4;
        const float* xp = x + (size_t)row0 * D;
        float*       op = out + (size_t)row0 * D;

        ull h0[RS], h1[RS];
#pragma unroll
        for (int r = 0; r < RS; r++) {
            const float* hb = g_hs + r * ROWS + row0;
            h0[r] = pk(hb[0], hb[1]);
            h1[r] = pk(hb[2], hb[3]);
        }
        // stage gg for this tile in per-warp smem
        __syncwarp();
        if (lane < RF) {
            const float* gp = g_g + (size_t)row0 * RF + lane;
            gw[lane * 2]     = pk(gp[0],      gp[RF]);
            gw[lane * 2 + 1] = pk(gp[2 * RF], gp[3 * RF]);
        }
        __syncwarp();

        float4 xa = *(const float4*)(xp + lane * 4);
        float4 xb = *(const float4*)(xp + D + lane * 4);
        float4 xc = *(const float4*)(xp + 2 * D + lane * 4);
        float4 xd = *(const float4*)(xp + 3 * D + lane * 4);

#pragma unroll 1
        for (int it = 0; it < 16; it++) {
            int d0 = it * 128 + lane * 4;
            float4 na, nb, nc, nd;
            if (it != 15) {
                int dn = d0 + 128;
                na = *(const float4*)(xp + dn);
                nb = *(const float4*)(xp + D + dn);
                nc = *(const float4*)(xp + 2 * D + dn);
                nd = *(const float4*)(xp + 3 * D + dn);
            }
            float A[4], Bv[4], C[4], Dv[4];
            *(float4*)A = xa; *(float4*)Bv = xb; *(float4*)C = xc; *(float4*)Dv = xd;

            float vv[RS][4];
#pragma unroll
            for (int r = 0; r < RS; r++)
                *(float4*)vv[r] = *(const float4*)(Vs + r * D + d0);

            ull o0[4], o1[4];
#pragma unroll
            for (int d = 0; d < 4; d++) {
                ull p0 = pk(A[d], Bv[d]);
                ull p1 = pk(C[d], Dv[d]);
#pragma unroll
                for (int r = 0; r < RS; r++) {
                    ull v2 = pk1(vv[r][d]);
                    p0 = f2fma(h0[r], v2, p0);
                    p1 = f2fma(h1[r], v2, p1);
                }
                o0[d] = p0; o1[d] = p1;
            }
#pragma unroll
            for (int j = 0; j < RF; j++) {
                ulonglong2 gj = *(const ulonglong2*)(gw + j * 2);  // broadcast LDS.128
                float wv[4];
                *(float4*)wv = *(const float4*)(W2s + j * D + d0);
#pragma unroll
                for (int d = 0; d < 4; d++) {
                    ull w2p = pk1(wv[d]);
                    o0[d] = f2fma(gj.x, w2p, o0[d]);
                    o1[d] = f2fma(gj.y, w2p, o1[d]);
                }
            }
            float oa[4], ob[4], oc[4], od[4];
#pragma unroll
            for (int d = 0; d < 4; d++) {
                upk(o0[d], oa[d], ob[d]);
                upk(o1[d], oc[d], od[d]);
            }
            *(float4*)(op + d0)         = *(float4*)oa;
            *(float4*)(op + D + d0)     = *(float4*)ob;
            *(float4*)(op + 2 * D + d0) = *(float4*)oc;
            *(float4*)(op + 3 * D + d0) = *(float4*)od;

            xa = na; xb = nb; xc = nc; xd = nd;
        }
    }
}

// ============================================================================
extern "C" void kernel_launch(void* const* d_in, const int* in_sizes, int n_in,
                              void* d_out, int out_size) {
    const float* x   = (const float*)d_in[0];
    const float* n1w = (const float*)d_in[1];
    const float* U   = (const float*)d_in[2];
    const float* lam = (const float*)d_in[3];
    const float* V   = (const float*)d_in[4];
    const float* n2w = (const float*)d_in[5];
    const float* W1  = (const float*)d_in[6];
    const float* W2  = (const float*)d_in[7];
    float* out = (float*)d_out;

    const int smem1  = RS * D * (int)sizeof(float);            // 48 KB
    const int smem3a = (RS + RF) * D * (int)sizeof(float);     // 216 KB
    const int smem3b = smem3a + (T3B / 32) * RF * 2 * (int)sizeof(ull); // +5.25 KB

    cudaFuncSetAttribute(k1_kernel,
                         cudaFuncAttributeMaxDynamicSharedMemorySize, smem1);
    cudaFuncSetAttribute(k3a_kernel,
                         cudaFuncAttributeMaxDynamicSharedMemorySize, smem3a);
    cudaFuncSetAttribute(k3b_kernel,
                         cudaFuncAttributeMaxDynamicSharedMemorySize, smem3b);

    k1_kernel<<<512, 256, smem1>>>(x, n1w, U);
    k2_scan<<<BB * RS, 128>>>(lam);
    k3a_kernel<<<148, T3A, smem3a>>>(x, V, n2w, W1);
    k3b_kernel<<<148, T3B, smem3b>>>(x, V, W2, out);
}

// round 14
// speedup vs baseline: 1.3083x; 1.2662x over previous
#include <cuda_runtime.h>

#define D     2048
#define SEQ   4096
#define BB    4
#define ROWS  16384      // BB*SEQ
#define RS    6          // ar_ssm rank
#define RF    21         // ffn rank
#define EPS   1e-6f

typedef unsigned long long ull;

// scratch (device globals — no allocations allowed)
__device__ float g_u [RS * ROWS];   // u transposed: [r][row]
__device__ float g_hs[RS * ROWS];   // scan states transposed: [r][row]
__device__ float g_g [ROWS * RF];   // gelu(t) per row

// -------- f32x2 helpers --------
__device__ __forceinline__ ull pk(float a, float b) {
    ull r; asm("mov.b64 %0,{%1,%2};" : "=l"(r) : "f"(a), "f"(b)); return r;
}
__device__ __forceinline__ ull pk1(float a) { return pk(a, a); }
__device__ __forceinline__ ull f2fma(ull a, ull b, ull c) {
    ull d; asm("fma.rn.f32x2 %0,%1,%2,%3;" : "=l"(d) : "l"(a), "l"(b), "l"(c));
    return d;
}
__device__ __forceinline__ void upk(ull v, float& a, float& b) {
    asm("mov.b64 {%0,%1},%2;" : "=f"(a), "=f"(b) : "l"(v));
}
__device__ __forceinline__ float wred(float v) {
#pragma unroll
    for (int off = 16; off > 0; off >>= 1)
        v += __shfl_xor_sync(0xffffffffu, v, off);
    return v;
}

// ============================================================================
// K1: per-row ssq(x) and u = rmsnorm(x,w1) @ U   (U*w1 folded into smem).
// 4 rows per warp; row pairs packed into f32x2; prefetched x loads.
// ============================================================================
__global__ void __launch_bounds__(256) k1_kernel(const float* __restrict__ x,
                                                 const float* __restrict__ w1,
                                                 const float* __restrict__ U) {
    extern __shared__ float Us[];                 // [RS][D]
    int tid = threadIdx.x;
    for (int d = tid; d < D; d += 256) {
        float w = w1[d];
#pragma unroll
        for (int r = 0; r < RS; r++) Us[r * D + d] = U[d * RS + r] * w;
    }
    __syncthreads();

    int lane = tid & 31;
    int gw = (blockIdx.x * 256 + tid) >> 5;
    int nw = (gridDim.x * 256) >> 5;

    for (int tile = gw; tile < ROWS / 4; tile += nw) {
        int row0 = tile * 4;
        const float* xp = x + (size_t)row0 * D;

        ull ss0 = 0ull, ss1 = 0ull;
        ull u20[RS], u21[RS];
#pragma unroll
        for (int r = 0; r < RS; r++) { u20[r] = 0ull; u21[r] = 0ull; }

        float4 xa = *(const float4*)(xp + lane * 4);
        float4 xb = *(const float4*)(xp + D + lane * 4);
        float4 xc = *(const float4*)(xp + 2 * D + lane * 4);
        float4 xd = *(const float4*)(xp + 3 * D + lane * 4);

#pragma unroll 1
        for (int it = 0; it < 16; it++) {
            int d0 = it * 128 + lane * 4;
            float4 na, nb, nc, nd;
            if (it != 15) {
                int dn = d0 + 128;
                na = *(const float4*)(xp + dn);
                nb = *(const float4*)(xp + D + dn);
                nc = *(const float4*)(xp + 2 * D + dn);
                nd = *(const float4*)(xp + 3 * D + dn);
            }
            float A[4], Bv[4], C[4], Dv[4];
            *(float4*)A = xa; *(float4*)Bv = xb; *(float4*)C = xc; *(float4*)Dv = xd;

            float uw[RS][4];
#pragma unroll
            for (int r = 0; r < RS; r++)
                *(float4*)uw[r] = *(const float4*)(Us + r * D + d0);
#pragma unroll
            for (int d = 0; d < 4; d++) {
                ull p0 = pk(A[d], Bv[d]);
                ull p1 = pk(C[d], Dv[d]);
                ss0 = f2fma(p0, p0, ss0);
                ss1 = f2fma(p1, p1, ss1);
#pragma unroll
                for (int r = 0; r < RS; r++) {
                    ull w2 = pk1(uw[r][d]);
                    u20[r] = f2fma(p0, w2, u20[r]);
                    u21[r] = f2fma(p1, w2, u21[r]);
                }
            }
            xa = na; xb = nb; xc = nc; xd = nd;
        }
        float ss[4], myu[4];
        { float a, b; upk(ss0, a, b); ss[0] = a; ss[1] = b;
                      upk(ss1, a, b); ss[2] = a; ss[3] = b; }
#pragma unroll
        for (int rr = 0; rr < 4; rr++) ss[rr] = wred(ss[rr]);
#pragma unroll
        for (int r = 0; r < RS; r++) {
            float a, b;
            upk(u20[r], a, b);
            a = wred(a); b = wred(b);
            if (lane == r) { myu[0] = a; myu[1] = b; }
            upk(u21[r], a, b);
            a = wred(a); b = wred(b);
            if (lane == r) { myu[2] = a; myu[3] = b; }
        }
#pragma unroll
        for (int rr = 0; rr < 4; rr++) {
            float inv = rsqrtf(ss[rr] * (1.0f / D) + EPS);
            if (lane < RS) g_u[lane * ROWS + row0 + rr] = inv * myu[rr];
        }
    }
}

// ============================================================================
// K2: linear recurrence h_s = a*h_{s-1} + u_s along S, per (b,r).
// ============================================================================
__global__ void __launch_bounds__(128) k2_scan(const float* __restrict__ lam) {
    int b = blockIdx.x / RS, r = blockIdx.x % RS;
    float a = 1.0f / (1.0f + expf(-lam[r]));
    const float* up = g_u  + r * ROWS + b * SEQ;
    float*       hp = g_hs + r * ROWS + b * SEQ;
    int t = threadIdx.x;
    const int L = 32;

    float loc[L];
#pragma unroll
    for (int kk = 0; kk < L / 4; kk++)
        *(float4*)(loc + kk * 4) = *(const float4*)(up + t * L + kk * 4);

    float h = 0.0f;
#pragma unroll
    for (int k = 0; k < L; k++) { h = a * h + loc[k]; loc[k] = h; }

    float aL = a;
#pragma unroll
    for (int i = 0; i < 5; i++) aL = aL * aL;     // a^32

    __shared__ float sf[128];
    float T = h;
    sf[t] = T;
    __syncthreads();
    float m = aL;
    for (int off = 1; off < 128; off <<= 1) {
        float prev = (t >= off) ? sf[t - off] : 0.0f;
        __syncthreads();
        T += m * prev;
        sf[t] = T;
        m = m * m;
        __syncthreads();
    }
    float Hin = (t > 0) ? sf[t - 1] : 0.0f;
    float p = a;
#pragma unroll
    for (int k = 0; k < L; k++) { loc[k] = loc[k] + p * Hin; p *= a; }
#pragma unroll
    for (int kk = 0; kk < L / 4; kk++)
        *(float4*)(hp + t * L + kk * 4) = *(const float4*)(loc + kk * 4);
}

// ============================================================================
// K3a: x1 = x + h@V (recomputed); ssq(x1); t = (w2*x1/rms)@W1; g = gelu(t).
// V + W1^T*w2 in smem (216KB). 320 threads (10 warps, reg cap 204, balanced).
// ============================================================================
#define T3A 320
__global__ void __launch_bounds__(T3A) k3a_kernel(const float* __restrict__ x,
                                                  const float* __restrict__ V,
                                                  const float* __restrict__ w2,
                                                  const float* __restrict__ W1) {
    extern __shared__ float sm[];
    float* Vs  = sm;              // [RS][D]
    float* W1s = sm + RS * D;     // [RF][D] transposed, * norm2_w
    int tid = threadIdx.x;
    for (int i = tid; i < RS * D; i += T3A) Vs[i] = V[i];
    for (int d = tid; d < D; d += T3A) {
        float w = w2[d];
#pragma unroll
        for (int j = 0; j < RF; j++) W1s[j * D + d] = W1[d * RF + j] * w;
    }
    __syncthreads();

    int lane = tid & 31;
    int gw = (blockIdx.x * T3A + tid) >> 5;
    int nw = (gridDim.x * T3A) >> 5;

    for (int tile = gw; tile < ROWS / 4; tile += nw) {
        int row0 = tile * 4;
        const float* xp = x + (size_t)row0 * D;

        ull h0[RS], h1[RS];
#pragma unroll
        for (int r = 0; r < RS; r++) {
            const float* hb = g_hs + r * ROWS + row0;
            h0[r] = pk(hb[0], hb[1]);
            h1[r] = pk(hb[2], hb[3]);
        }
        ull ss0 = 0ull, ss1 = 0ull;
        ull t0[RF], t1[RF];
#pragma unroll
        for (int j = 0; j < RF; j++) { t0[j] = 0ull; t1[j] = 0ull; }

        float4 xa = *(const float4*)(xp + lane * 4);
        float4 xb = *(const float4*)(xp + D + lane * 4);
        float4 xc = *(const float4*)(xp + 2 * D + lane * 4);
        float4 xd = *(const float4*)(xp + 3 * D + lane * 4);

#pragma unroll 1
        for (int it = 0; it < 16; it++) {
            int d0 = it * 128 + lane * 4;
            float4 na, nb, nc, nd;
            if (it != 15) {
                int dn = d0 + 128;
                na = *(const float4*)(xp + dn);
                nb = *(const float4*)(xp + D + dn);
                nc = *(const float4*)(xp + 2 * D + dn);
                nd = *(const float4*)(xp + 3 * D + dn);
            }
            float A[4], Bv[4], C[4], Dv[4];
            *(float4*)A = xa; *(float4*)Bv = xb; *(float4*)C = xc; *(float4*)Dv = xd;

            float vv[RS][4];
#pragma unroll
            for (int r = 0; r < RS; r++)
                *(float4*)vv[r] = *(const float4*)(Vs + r * D + d0);

            ull x10[4], x11[4];
#pragma unroll
            for (int d = 0; d < 4; d++) {
                ull p0 = pk(A[d], Bv[d]);
                ull p1 = pk(C[d], Dv[d]);
#pragma unroll
                for (int r = 0; r < RS; r++) {
                    ull v2 = pk1(vv[r][d]);
                    p0 = f2fma(h0[r], v2, p0);
                    p1 = f2fma(h1[r], v2, p1);
                }
                x10[d] = p0; x11[d] = p1;
                ss0 = f2fma(p0, p0, ss0);
                ss1 = f2fma(p1, p1, ss1);
            }
#pragma unroll
            for (int j = 0; j < RF; j++) {
                float wv[4];
                *(float4*)wv = *(const float4*)(W1s + j * D + d0);
#pragma unroll
                for (int d = 0; d < 4; d++) {
                    ull w2p = pk1(wv[d]);
                    t0[j] = f2fma(x10[d], w2p, t0[j]);
                    t1[j] = f2fma(x11[d], w2p, t1[j]);
                }
            }
            xa = na; xb = nb; xc = nc; xd = nd;
        }
        float ss[4], myt[4];
        { float a, b; upk(ss0, a, b); ss[0] = a; ss[1] = b;
                      upk(ss1, a, b); ss[2] = a; ss[3] = b; }
#pragma unroll
        for (int rr = 0; rr < 4; rr++) ss[rr] = wred(ss[rr]);
#pragma unroll
        for (int j = 0; j < RF; j++) {
            float a, b;
            upk(t0[j], a, b);
            a = wred(a); b = wred(b);
            if (lane == j) { myt[0] = a; myt[1] = b; }
            upk(t1[j], a, b);
            a = wred(a); b = wred(b);
            if (lane == j) { myt[2] = a; myt[3] = b; }
        }
#pragma unroll
        for (int rr = 0; rr < 4; rr++) {
            float inv = rsqrtf(ss[rr] * (1.0f / D) + EPS);
            if (lane < RF) {
                float tv = inv * myt[rr];
                float g = 0.5f * tv *
                    (1.0f + tanhf(0.7978845608028654f * (tv + 0.044715f * tv * tv * tv)));
                g_g[(size_t)(row0 + rr) * RF + lane] = g;
            }
        }
    }
}

// ============================================================================
// K3b: out = (x + h@V) + g @ W2.
// 448 threads (14 warps/SM, reg cap 146, 2072 warps -> balanced 2 tiles/warp);
// gg staged in per-warp smem; prefetched x loads; streaming stores.
// ============================================================================
#define T3B 448
__global__ void __launch_bounds__(T3B) k3b_kernel(const float* __restrict__ x,
                                                  const float* __restrict__ V,
                                                  const float* __restrict__ W2,
                                                  float* __restrict__ out) {
    extern __shared__ float sm[];
    float* Vs  = sm;              // [RS][D]
    float* W2s = sm + RS * D;     // [RF][D]
    ull*   gW  = (ull*)(sm + (RS + RF) * D);   // [nwarps][RF][2]
    int tid = threadIdx.x;
    for (int i = tid; i < RS * D; i += T3B) Vs[i] = V[i];
    for (int i = tid; i < RF * D; i += T3B) W2s[i] = W2[i];
    __syncthreads();

    int lane = tid & 31;
    int wid = tid >> 5;
    ull* gw = gW + wid * (RF * 2);

    int gwid = (blockIdx.x * T3B + tid) >> 5;
    int nw = (gridDim.x * T3B) >> 5;

    for (int tile = gwid; tile < ROWS / 4; tile += nw) {
        int row0 = tile * 4;
        const float* xp = x + (size_t)row0 * D;
        float*       op = out + (size_t)row0 * D;

        ull h0[RS], h1[RS];
#pragma unroll
        for (int r = 0; r < RS; r++) {
            const float* hb = g_hs + r * ROWS + row0;
            h0[r] = pk(hb[0], hb[1]);
            h1[r] = pk(hb[2], hb[3]);
        }
        // stage gg for this tile in per-warp smem
        __syncwarp();
        if (lane < RF) {
            const float* gp = g_g + (size_t)row0 * RF + lane;
            gw[lane * 2]     = pk(gp[0],      gp[RF]);
            gw[lane * 2 + 1] = pk(gp[2 * RF], gp[3 * RF]);
        }
        __syncwarp();

        float4 xa = *(const float4*)(xp + lane * 4);
        float4 xb = *(const float4*)(xp + D + lane * 4);
        float4 xc = *(const float4*)(xp + 2 * D + lane * 4);
        float4 xd = *(const float4*)(xp + 3 * D + lane * 4);

#pragma unroll 1
        for (int it = 0; it < 16; it++) {
            int d0 = it * 128 + lane * 4;
            float4 na, nb, nc, nd;
            if (it != 15) {
                int dn = d0 + 128;
                na = *(const float4*)(xp + dn);
                nb = *(const float4*)(xp + D + dn);
                nc = *(const float4*)(xp + 2 * D + dn);
                nd = *(const float4*)(xp + 3 * D + dn);
            }
            float A[4], Bv[4], C[4], Dv[4];
            *(float4*)A = xa; *(float4*)Bv = xb; *(float4*)C = xc; *(float4*)Dv = xd;

            float vv[RS][4];
#pragma unroll
            for (int r = 0; r < RS; r++)
                *(float4*)vv[r] = *(const float4*)(Vs + r * D + d0);

            ull o0[4], o1[4];
#pragma unroll
            for (int d = 0; d < 4; d++) {
                ull p0 = pk(A[d], Bv[d]);
                ull p1 = pk(C[d], Dv[d]);
#pragma unroll
                for (int r = 0; r < RS; r++) {
                    ull v2 = pk1(vv[r][d]);
                    p0 = f2fma(h0[r], v2, p0);
                    p1 = f2fma(h1[r], v2, p1);
                }
                o0[d] = p0; o1[d] = p1;
            }
#pragma unroll
            for (int j = 0; j < RF; j++) {
                ulonglong2 gj = *(const ulonglong2*)(gw + j * 2);  // broadcast LDS.128
                float wv[4];
                *(float4*)wv = *(const float4*)(W2s + j * D + d0);
#pragma unroll
                for (int d = 0; d < 4; d++) {
                    ull w2p = pk1(wv[d]);
                    o0[d] = f2fma(gj.x, w2p, o0[d]);
                    o1[d] = f2fma(gj.y, w2p, o1[d]);
                }
            }
            float oa[4], ob[4], oc[4], od[4];
#pragma unroll
            for (int d = 0; d < 4; d++) {
                upk(o0[d], oa[d], ob[d]);
                upk(o1[d], oc[d], od[d]);
            }
            __stcs((float4*)(op + d0),         *(float4*)oa);
            __stcs((float4*)(op + D + d0),     *(float4*)ob);
            __stcs((float4*)(op + 2 * D + d0), *(float4*)oc);
            __stcs((float4*)(op + 3 * D + d0), *(float4*)od);

            xa = na; xb = nb; xc = nc; xd = nd;
        }
    }
}

// ============================================================================
extern "C" void kernel_launch(void* const* d_in, const int* in_sizes, int n_in,
                              void* d_out, int out_size) {
    const float* x   = (const float*)d_in[0];
    const float* n1w = (const float*)d_in[1];
    const float* U   = (const float*)d_in[2];
    const float* lam = (const float*)d_in[3];
    const float* V   = (const float*)d_in[4];
    const float* n2w = (const float*)d_in[5];
    const float* W1  = (const float*)d_in[6];
    const float* W2  = (const float*)d_in[7];
    float* out = (float*)d_out;

    const int smem1  = RS * D * (int)sizeof(float);            // 48 KB
    const int smem3a = (RS + RF) * D * (int)sizeof(float);     // 216 KB
    const int smem3b = smem3a + (T3B / 32) * RF * 2 * (int)sizeof(ull);

    cudaFuncSetAttribute(k1_kernel,
                         cudaFuncAttributeMaxDynamicSharedMemorySize, smem1);
    cudaFuncSetAttribute(k3a_kernel,
                         cudaFuncAttributeMaxDynamicSharedMemorySize, smem3a);
    cudaFuncSetAttribute(k3b_kernel,
                         cudaFuncAttributeMaxDynamicSharedMemorySize, smem3b);

    k1_kernel<<<592, 256, smem1>>>(x, n1w, U);          // 4 CTAs/SM
    k2_scan<<<BB * RS, 128>>>(lam);
    k3a_kernel<<<148, T3A, smem3a>>>(x, V, n2w, W1);
    k3b_kernel<<<148, T3B, smem3b>>>(x, V, W2, out);
}

// round 15
// speedup vs baseline: 1.3105x; 1.0017x over previous
#include <cuda_runtime.h>

#define D     2048
#define SEQ   4096
#define BB    4
#define ROWS  16384      // BB*SEQ
#define RS    6          // ar_ssm rank
#define RF    21         // ffn rank
#define EPS   1e-6f

typedef unsigned long long ull;

// scratch (device globals — no allocations allowed)
__device__ float g_u [RS * ROWS];   // u transposed: [r][row]
__device__ float g_hs[RS * ROWS];   // scan states transposed: [r][row]
__device__ float g_g [ROWS * RF];   // gelu(t) per row

// -------- f32x2 helpers --------
__device__ __forceinline__ ull pk(float a, float b) {
    ull r; asm("mov.b64 %0,{%1,%2};" : "=l"(r) : "f"(a), "f"(b)); return r;
}
__device__ __forceinline__ ull pk1(float a) { return pk(a, a); }
__device__ __forceinline__ ull f2fma(ull a, ull b, ull c) {
    ull d; asm("fma.rn.f32x2 %0,%1,%2,%3;" : "=l"(d) : "l"(a), "l"(b), "l"(c));
    return d;
}
__device__ __forceinline__ void upk(ull v, float& a, float& b) {
    asm("mov.b64 {%0,%1},%2;" : "=f"(a), "=f"(b) : "l"(v));
}
__device__ __forceinline__ float wred(float v) {
#pragma unroll
    for (int off = 16; off > 0; off >>= 1)
        v += __shfl_xor_sync(0xffffffffu, v, off);
    return v;
}

// ============================================================================
// K1: per-row ssq(x) and u = rmsnorm(x,w1) @ U   (U*w1 folded into smem).
// 4 rows per warp; row pairs packed into f32x2; prefetched x loads.
// ============================================================================
__global__ void __launch_bounds__(256) k1_kernel(const float* __restrict__ x,
                                                 const float* __restrict__ w1,
                                                 const float* __restrict__ U) {
    extern __shared__ float Us[];                 // [RS][D]
    int tid = threadIdx.x;
    for (int d = tid; d < D; d += 256) {
        float w = w1[d];
#pragma unroll
        for (int r = 0; r < RS; r++) Us[r * D + d] = U[d * RS + r] * w;
    }
    __syncthreads();

    int lane = tid & 31;
    int gw = (blockIdx.x * 256 + tid) >> 5;
    int nw = (gridDim.x * 256) >> 5;

    for (int tile = gw; tile < ROWS / 4; tile += nw) {
        int row0 = tile * 4;
        const float* xp = x + (size_t)row0 * D;

        ull ss0 = 0ull, ss1 = 0ull;
        ull u20[RS], u21[RS];
#pragma unroll
        for (int r = 0; r < RS; r++) { u20[r] = 0ull; u21[r] = 0ull; }

        float4 xa = *(const float4*)(xp + lane * 4);
        float4 xb = *(const float4*)(xp + D + lane * 4);
        float4 xc = *(const float4*)(xp + 2 * D + lane * 4);
        float4 xd = *(const float4*)(xp + 3 * D + lane * 4);

#pragma unroll 1
        for (int it = 0; it < 16; it++) {
            int d0 = it * 128 + lane * 4;
            float4 na, nb, nc, nd;
            if (it != 15) {
                int dn = d0 + 128;
                na = *(const float4*)(xp + dn);
                nb = *(const float4*)(xp + D + dn);
                nc = *(const float4*)(xp + 2 * D + dn);
                nd = *(const float4*)(xp + 3 * D + dn);
            }
            float A[4], Bv[4], C[4], Dv[4];
            *(float4*)A = xa; *(float4*)Bv = xb; *(float4*)C = xc; *(float4*)Dv = xd;

            float uw[RS][4];
#pragma unroll
            for (int r = 0; r < RS; r++)
                *(float4*)uw[r] = *(const float4*)(Us + r * D + d0);
#pragma unroll
            for (int d = 0; d < 4; d++) {
                ull p0 = pk(A[d], Bv[d]);
                ull p1 = pk(C[d], Dv[d]);
                ss0 = f2fma(p0, p0, ss0);
                ss1 = f2fma(p1, p1, ss1);
#pragma unroll
                for (int r = 0; r < RS; r++) {
                    ull w2 = pk1(uw[r][d]);
                    u20[r] = f2fma(p0, w2, u20[r]);
                    u21[r] = f2fma(p1, w2, u21[r]);
                }
            }
            xa = na; xb = nb; xc = nc; xd = nd;
        }
        float ss[4], myu[4];
        { float a, b; upk(ss0, a, b); ss[0] = a; ss[1] = b;
                      upk(ss1, a, b); ss[2] = a; ss[3] = b; }
#pragma unroll
        for (int rr = 0; rr < 4; rr++) ss[rr] = wred(ss[rr]);
#pragma unroll
        for (int r = 0; r < RS; r++) {
            float a, b;
            upk(u20[r], a, b);
            a = wred(a); b = wred(b);
            if (lane == r) { myu[0] = a; myu[1] = b; }
            upk(u21[r], a, b);
            a = wred(a); b = wred(b);
            if (lane == r) { myu[2] = a; myu[3] = b; }
        }
#pragma unroll
        for (int rr = 0; rr < 4; rr++) {
            float inv = rsqrtf(ss[rr] * (1.0f / D) + EPS);
            if (lane < RS) g_u[lane * ROWS + row0 + rr] = inv * myu[rr];
        }
    }
}

// ============================================================================
// K2: linear recurrence h_s = a*h_{s-1} + u_s along S, per (b,r).
// ============================================================================
__global__ void __launch_bounds__(128) k2_scan(const float* __restrict__ lam) {
    int b = blockIdx.x / RS, r = blockIdx.x % RS;
    float a = 1.0f / (1.0f + expf(-lam[r]));
    const float* up = g_u  + r * ROWS + b * SEQ;
    float*       hp = g_hs + r * ROWS + b * SEQ;
    int t = threadIdx.x;
    const int L = 32;

    float loc[L];
#pragma unroll
    for (int kk = 0; kk < L / 4; kk++)
        *(float4*)(loc + kk * 4) = *(const float4*)(up + t * L + kk * 4);

    float h = 0.0f;
#pragma unroll
    for (int k = 0; k < L; k++) { h = a * h + loc[k]; loc[k] = h; }

    float aL = a;
#pragma unroll
    for (int i = 0; i < 5; i++) aL = aL * aL;     // a^32

    __shared__ float sf[128];
    float T = h;
    sf[t] = T;
    __syncthreads();
    float m = aL;
    for (int off = 1; off < 128; off <<= 1) {
        float prev = (t >= off) ? sf[t - off] : 0.0f;
        __syncthreads();
        T += m * prev;
        sf[t] = T;
        m = m * m;
        __syncthreads();
    }
    float Hin = (t > 0) ? sf[t - 1] : 0.0f;
    float p = a;
#pragma unroll
    for (int k = 0; k < L; k++) { loc[k] = loc[k] + p * Hin; p *= a; }
#pragma unroll
    for (int kk = 0; kk < L / 4; kk++)
        *(float4*)(hp + t * L + kk * 4) = *(const float4*)(loc + kk * 4);
}

// ============================================================================
// K3a: x1 = x + h@V (recomputed); ssq(x1); t = (w2*x1/rms)@W1; g = gelu(t).
// V + W1^T*w2 in smem (216KB). 320 threads (10 warps, reg cap 204, balanced).
// ============================================================================
#define T3A 320
__global__ void __launch_bounds__(T3A) k3a_kernel(const float* __restrict__ x,
                                                  const float* __restrict__ V,
                                                  const float* __restrict__ w2,
                                                  const float* __restrict__ W1) {
    extern __shared__ float sm[];
    float* Vs  = sm;              // [RS][D]
    float* W1s = sm + RS * D;     // [RF][D] transposed, * norm2_w
    int tid = threadIdx.x;
    for (int i = tid; i < RS * D; i += T3A) Vs[i] = V[i];
    for (int d = tid; d < D; d += T3A) {
        float w = w2[d];
#pragma unroll
        for (int j = 0; j < RF; j++) W1s[j * D + d] = W1[d * RF + j] * w;
    }
    __syncthreads();

    int lane = tid & 31;
    int gw = (blockIdx.x * T3A + tid) >> 5;
    int nw = (gridDim.x * T3A) >> 5;

    for (int tile = gw; tile < ROWS / 4; tile += nw) {
        int row0 = tile * 4;
        const float* xp = x + (size_t)row0 * D;

        ull h0[RS], h1[RS];
#pragma unroll
        for (int r = 0; r < RS; r++) {
            const float* hb = g_hs + r * ROWS + row0;
            h0[r] = pk(hb[0], hb[1]);
            h1[r] = pk(hb[2], hb[3]);
        }
        ull ss0 = 0ull, ss1 = 0ull;
        ull t0[RF], t1[RF];
#pragma unroll
        for (int j = 0; j < RF; j++) { t0[j] = 0ull; t1[j] = 0ull; }

        float4 xa = *(const float4*)(xp + lane * 4);
        float4 xb = *(const float4*)(xp + D + lane * 4);
        float4 xc = *(const float4*)(xp + 2 * D + lane * 4);
        float4 xd = *(const float4*)(xp + 3 * D + lane * 4);

#pragma unroll 1
        for (int it = 0; it < 16; it++) {
            int d0 = it * 128 + lane * 4;
            float4 na, nb, nc, nd;
            if (it != 15) {
                int dn = d0 + 128;
                na = *(const float4*)(xp + dn);
                nb = *(const float4*)(xp + D + dn);
                nc = *(const float4*)(xp + 2 * D + dn);
                nd = *(const float4*)(xp + 3 * D + dn);
            }
            float A[4], Bv[4], C[4], Dv[4];
            *(float4*)A = xa; *(float4*)Bv = xb; *(float4*)C = xc; *(float4*)Dv = xd;

            float vv[RS][4];
#pragma unroll
            for (int r = 0; r < RS; r++)
                *(float4*)vv[r] = *(const float4*)(Vs + r * D + d0);

            ull x10[4], x11[4];
#pragma unroll
            for (int d = 0; d < 4; d++) {
                ull p0 = pk(A[d], Bv[d]);
                ull p1 = pk(C[d], Dv[d]);
#pragma unroll
                for (int r = 0; r < RS; r++) {
                    ull v2 = pk1(vv[r][d]);
                    p0 = f2fma(h0[r], v2, p0);
                    p1 = f2fma(h1[r], v2, p1);
                }
                x10[d] = p0; x11[d] = p1;
                ss0 = f2fma(p0, p0, ss0);
                ss1 = f2fma(p1, p1, ss1);
            }
#pragma unroll
            for (int j = 0; j < RF; j++) {
                float wv[4];
                *(float4*)wv = *(const float4*)(W1s + j * D + d0);
#pragma unroll
                for (int d = 0; d < 4; d++) {
                    ull w2p = pk1(wv[d]);
                    t0[j] = f2fma(x10[d], w2p, t0[j]);
                    t1[j] = f2fma(x11[d], w2p, t1[j]);
                }
            }
            xa = na; xb = nb; xc = nc; xd = nd;
        }
        float ss[4], myt[4];
        { float a, b; upk(ss0, a, b); ss[0] = a; ss[1] = b;
                      upk(ss1, a, b); ss[2] = a; ss[3] = b; }
#pragma unroll
        for (int rr = 0; rr < 4; rr++) ss[rr] = wred(ss[rr]);
#pragma unroll
        for (int j = 0; j < RF; j++) {
            float a, b;
            upk(t0[j], a, b);
            a = wred(a); b = wred(b);
            if (lane == j) { myt[0] = a; myt[1] = b; }
            upk(t1[j], a, b);
            a = wred(a); b = wred(b);
            if (lane == j) { myt[2] = a; myt[3] = b; }
        }
#pragma unroll
        for (int rr = 0; rr < 4; rr++) {
            float inv = rsqrtf(ss[rr] * (1.0f / D) + EPS);
            if (lane < RF) {
                float tv = inv * myt[rr];
                float g = 0.5f * tv *
                    (1.0f + tanhf(0.7978845608028654f * (tv + 0.044715f * tv * tv * tv)));
                g_g[(size_t)(row0 + rr) * RF + lane] = g;
            }
        }
    }
}

// ============================================================================
// K3b: out = (x + h@V) + g @ W2.
// 448 threads (14 warps/SM, reg cap 146, 2072 warps -> balanced 2 tiles/warp);
// gg staged in per-warp smem; prefetched x loads; streaming stores.
// ============================================================================
#define T3B 448
__global__ void __launch_bounds__(T3B) k3b_kernel(const float* __restrict__ x,
                                                  const float* __restrict__ V,
                                                  const float* __restrict__ W2,
                                                  float* __restrict__ out) {
    extern __shared__ float sm[];
    float* Vs  = sm;              // [RS][D]
    float* W2s = sm + RS * D;     // [RF][D]
    ull*   gW  = (ull*)(sm + (RS + RF) * D);   // [nwarps][RF][2]
    int tid = threadIdx.x;
    for (int i = tid; i < RS * D; i += T3B) Vs[i] = V[i];
    for (int i = tid; i < RF * D; i += T3B) W2s[i] = W2[i];
    __syncthreads();

    int lane = tid & 31;
    int wid = tid >> 5;
    ull* gw = gW + wid * (RF * 2);

    int gwid = (blockIdx.x * T3B + tid) >> 5;
    int nw = (gridDim.x * T3B) >> 5;

    for (int tile = gwid; tile < ROWS / 4; tile += nw) {
        int row0 = tile * 4;
        const float* xp = x + (size_t)row0 * D;
        float*       op = out + (size_t)row0 * D;

        ull h0[RS], h1[RS];
#pragma unroll
        for (int r = 0; r < RS; r++) {
            const float* hb = g_hs + r * ROWS + row0;
            h0[r] = pk(hb[0], hb[1]);
            h1[r] = pk(hb[2], hb[3]);
        }
        // stage gg for this tile in per-warp smem
        __syncwarp();
        if (lane < RF) {
            const float* gp = g_g + (size_t)row0 * RF + lane;
            gw[lane * 2]     = pk(gp[0],      gp[RF]);
            gw[lane * 2 + 1] = pk(gp[2 * RF], gp[3 * RF]);
        }
        __syncwarp();

        float4 xa = *(const float4*)(xp + lane * 4);
        float4 xb = *(const float4*)(xp + D + lane * 4);
        float4 xc = *(const float4*)(xp + 2 * D + lane * 4);
        float4 xd = *(const float4*)(xp + 3 * D + lane * 4);

#pragma unroll 1
        for (int it = 0; it < 16; it++) {
            int d0 = it * 128 + lane * 4;
            float4 na, nb, nc, nd;
            if (it != 15) {
                int dn = d0 + 128;
                na = *(const float4*)(xp + dn);
                nb = *(const float4*)(xp + D + dn);
                nc = *(const float4*)(xp + 2 * D + dn);
                nd = *(const float4*)(xp + 3 * D + dn);
            }
            float A[4], Bv[4], C[4], Dv[4];
            *(float4*)A = xa; *(float4*)Bv = xb; *(float4*)C = xc; *(float4*)Dv = xd;

            float vv[RS][4];
#pragma unroll
            for (int r = 0; r < RS; r++)
                *(float4*)vv[r] = *(const float4*)(Vs + r * D + d0);

            ull o0[4], o1[4];
#pragma unroll
            for (int d = 0; d < 4; d++) {
                ull p0 = pk(A[d], Bv[d]);
                ull p1 = pk(C[d], Dv[d]);
#pragma unroll
                for (int r = 0; r < RS; r++) {
                    ull v2 = pk1(vv[r][d]);
                    p0 = f2fma(h0[r], v2, p0);
                    p1 = f2fma(h1[r], v2, p1);
                }
                o0[d] = p0; o1[d] = p1;
            }
#pragma unroll
            for (int j = 0; j < RF; j++) {
                ulonglong2 gj = *(const ulonglong2*)(gw + j * 2);  // broadcast LDS.128
                float wv[4];
                *(float4*)wv = *(const float4*)(W2s + j * D + d0);
#pragma unroll
                for (int d = 0; d < 4; d++) {
                    ull w2p = pk1(wv[d]);
                    o0[d] = f2fma(gj.x, w2p, o0[d]);
                    o1[d] = f2fma(gj.y, w2p, o1[d]);
                }
            }
            float oa[4], ob[4], oc[4], od[4];
#pragma unroll
            for (int d = 0; d < 4; d++) {
                upk(o0[d], oa[d], ob[d]);
                upk(o1[d], oc[d], od[d]);
            }
            __stcs((float4*)(op + d0),         *(float4*)oa);
            __stcs((float4*)(op + D + d0),     *(float4*)ob);
            __stcs((float4*)(op + 2 * D + d0), *(float4*)oc);
            __stcs((float4*)(op + 3 * D + d0), *(float4*)od);

            xa = na; xb = nb; xc = nc; xd = nd;
        }
    }
}

// ============================================================================
extern "C" void kernel_launch(void* const* d_in, const int* in_sizes, int n_in,
                              void* d_out, int out_size) {
    const float* x   = (const float*)d_in[0];
    const float* n1w = (const float*)d_in[1];
    const float* U   = (const float*)d_in[2];
    const float* lam = (const float*)d_in[3];
    const float* V   = (const float*)d_in[4];
    const float* n2w = (const float*)d_in[5];
    const float* W1  = (const float*)d_in[6];
    const float* W2  = (const float*)d_in[7];
    float* out = (float*)d_out;

    const int smem1  = RS * D * (int)sizeof(float);            // 48 KB
    const int smem3a = (RS + RF) * D * (int)sizeof(float);     // 216 KB
    const int smem3b = smem3a + (T3B / 32) * RF * 2 * (int)sizeof(ull);

    cudaFuncSetAttribute(k1_kernel,
                         cudaFuncAttributeMaxDynamicSharedMemorySize, smem1);
    cudaFuncSetAttribute(k3a_kernel,
                         cudaFuncAttributeMaxDynamicSharedMemorySize, smem3a);
    cudaFuncSetAttribute(k3b_kernel,
                         cudaFuncAttributeMaxDynamicSharedMemorySize, smem3b);

    k1_kernel<<<592, 256, smem1>>>(x, n1w, U);          // 4 CTAs/SM
    k2_scan<<<BB * RS, 128>>>(lam);
    k3a_kernel<<<148, T3A, smem3a>>>(x, V, n2w, W1);
    k3b_kernel<<<148, T3B, smem3b>>>(x, V, W2, out);
}